// round 11
// baseline (speedup 1.0000x reference)
#include <cuda_runtime.h>
#include <cuda_bf16.h>
#include <mma.h>
#include <cstdint>

using namespace nvcuda;

#define Bn  64
#define Ssz 512
#define Dsz 512
#define Hsz 512
#define Gsz 2048   // 4*H

// recurrent tiling: 4 b-columns x 32 j-slices = 128 blocks, 256 threads each
#define NBS 4      // b-slices
#define NJ  32     // j-slice blocks per b-column
#define JT  16     // j per block
#define BT  16     // b per block

// ---------------------------------------------------------------------------
// global scratch
// ---------------------------------------------------------------------------
__device__ float         g_xg[(size_t)Ssz * Bn * Gsz];       // 256 MB
__device__ __nv_bfloat16 g_hsl[2][NBS][2][Hsz * BT];         // [ping][bs][hi/lo][j*16+bb]
__device__ unsigned      g_cnt[NBS * 32];                    // 128B-spaced counters
__device__ unsigned      g_done;
__device__ __nv_bfloat16 g_Ahi[(size_t)Bn * Ssz * Dsz];      // inputs hi
__device__ __nv_bfloat16 g_Alo[(size_t)Bn * Ssz * Dsz];      // inputs lo
__device__ __nv_bfloat16 g_Whi[(size_t)Gsz * Dsz];           // W_ih hi
__device__ __nv_bfloat16 g_Wlo[(size_t)Gsz * Dsz];           // W_ih lo

// ---------------------------------------------------------------------------
// light device-scope sync primitives (no membar.gl -> no L1 flush)
// ---------------------------------------------------------------------------
__device__ __forceinline__ void red_release(unsigned* p) {
    asm volatile("red.release.gpu.global.add.u32 [%0], 1;" :: "l"(p) : "memory");
}
__device__ __forceinline__ unsigned ld_acquire(unsigned* p) {
    unsigned v;
    asm volatile("ld.acquire.gpu.global.u32 %0, [%1];" : "=r"(v) : "l"(p) : "memory");
    return v;
}
// precise-enough tanh: 1 - 2/(e^{2x}+1); ~1e-6 rel err, 2 MUFU ops
__device__ __forceinline__ float tanh_cheap(float x) {
    return 1.0f - __fdividef(2.0f, __expf(2.0f * x) + 1.0f);
}

// ---------------------------------------------------------------------------
// dummy no-op kernel: shifts ncu's sampled launch index (-s 5 -c 1) so the
// 6th launch is lstm_rec, not convert_kernel. Deterministic, capturable.
// ---------------------------------------------------------------------------
__global__ void dummy_kernel() { }

// ---------------------------------------------------------------------------
// Kernel 1: fp32 -> (hi,lo) bf16 split for inputs (with emb shift) and W_ih
// ---------------------------------------------------------------------------
__global__ __launch_bounds__(256) void convert_kernel(
    const float* __restrict__ x, const float* __restrict__ emb,
    const float* __restrict__ W_ih)
{
    const int A4 = (Bn * Ssz * Dsz) / 4;
    const int T4 = A4 + (Gsz * Dsz) / 4;
    for (int idx = blockIdx.x * 256 + threadIdx.x; idx < T4; idx += gridDim.x * 256) {
        const float* src;
        __nv_bfloat16 *hi, *lo;
        int off4;
        if (idx < A4) {
            int m = idx >> 7, c = idx & 127;
            int s = m & 511;
            src = (s == 0) ? (emb + (size_t)(m >> 9) * Dsz)
                           : (x + (size_t)(m - 1) * Dsz);
            src += c * 4;
            hi = g_Ahi; lo = g_Alo; off4 = idx;
        } else {
            int i2 = idx - A4;
            src = W_ih + (size_t)i2 * 4;
            hi = g_Whi; lo = g_Wlo; off4 = i2;
        }
        float4 v = *(const float4*)src;
        __nv_bfloat162 h01, h23, l01, l23;
        h01.x = __float2bfloat16_rn(v.x); h01.y = __float2bfloat16_rn(v.y);
        h23.x = __float2bfloat16_rn(v.z); h23.y = __float2bfloat16_rn(v.w);
        l01.x = __float2bfloat16_rn(v.x - __bfloat162float(h01.x));
        l01.y = __float2bfloat16_rn(v.y - __bfloat162float(h01.y));
        l23.x = __float2bfloat16_rn(v.z - __bfloat162float(h23.x));
        l23.y = __float2bfloat16_rn(v.w - __bfloat162float(h23.y));
        uint2 hu, lu;
        hu.x = *(uint32_t*)&h01; hu.y = *(uint32_t*)&h23;
        lu.x = *(uint32_t*)&l01; lu.y = *(uint32_t*)&l23;
        ((uint2*)hi)[off4] = hu;
        ((uint2*)lo)[off4] = lu;
    }
}

// ---------------------------------------------------------------------------
// Kernel 2: WMMA bf16 split GEMM  xg = inputs @ W_ih^T + (b_ih + b_hh)
// (unchanged — works)
// ---------------------------------------------------------------------------
#define GBM 128
#define GBN 128
#define GKC 64
#define LDA 72
#define LDC 132
#define SM_GEMM_BYTES (4 * 128 * LDA * 2)

__global__ __launch_bounds__(256) void xg_gemm_mma(
    const float* __restrict__ b_ih, const float* __restrict__ b_hh)
{
    extern __shared__ char smem[];
    __nv_bfloat16* A_hi = (__nv_bfloat16*)smem;
    __nv_bfloat16* A_lo = A_hi + 128 * LDA;
    __nv_bfloat16* B_hi = A_lo + 128 * LDA;
    __nv_bfloat16* B_lo = B_hi + 128 * LDA;

    const int tid = threadIdx.x;
    const int wid = tid >> 5;
    const int m0 = blockIdx.y * GBM;
    const int n0 = blockIdx.x * GBN;
    const int wm = wid >> 1;
    const int wn = wid & 1;

    wmma::fragment<wmma::accumulator, 16, 16, 16, float> C[2][4];
#pragma unroll
    for (int i = 0; i < 2; i++)
#pragma unroll
        for (int j = 0; j < 4; j++) wmma::fill_fragment(C[i][j], 0.0f);

    for (int kc = 0; kc < Dsz / GKC; kc++) {
        const int k0 = kc * GKC;
#pragma unroll
        for (int u = 0; u < 4; u++) {
            int unit = u * 256 + tid;
            int row = unit >> 3, c8 = unit & 7;
            size_t ga = (size_t)(m0 + row) * Dsz + k0 + c8 * 8;
            size_t gb = (size_t)(n0 + row) * Dsz + k0 + c8 * 8;
            int so = row * LDA + c8 * 8;
            *(uint4*)(A_hi + so) = *(const uint4*)(g_Ahi + ga);
            *(uint4*)(A_lo + so) = *(const uint4*)(g_Alo + ga);
            *(uint4*)(B_hi + so) = *(const uint4*)(g_Whi + gb);
            *(uint4*)(B_lo + so) = *(const uint4*)(g_Wlo + gb);
        }
        __syncthreads();

#pragma unroll
        for (int kk = 0; kk < GKC / 16; kk++) {
            wmma::fragment<wmma::matrix_a, 16, 16, 16, __nv_bfloat16, wmma::row_major> ah[2], al[2];
            wmma::fragment<wmma::matrix_b, 16, 16, 16, __nv_bfloat16, wmma::col_major> bh[4], bl[4];
#pragma unroll
            for (int i = 0; i < 2; i++) {
                int ro = (wm * 32 + i * 16) * LDA + kk * 16;
                wmma::load_matrix_sync(ah[i], A_hi + ro, LDA);
                wmma::load_matrix_sync(al[i], A_lo + ro, LDA);
            }
#pragma unroll
            for (int j = 0; j < 4; j++) {
                int ro = (wn * 64 + j * 16) * LDA + kk * 16;
                wmma::load_matrix_sync(bh[j], B_hi + ro, LDA);
                wmma::load_matrix_sync(bl[j], B_lo + ro, LDA);
            }
#pragma unroll
            for (int i = 0; i < 2; i++)
#pragma unroll
                for (int j = 0; j < 4; j++) {
                    wmma::mma_sync(C[i][j], ah[i], bh[j], C[i][j]);
                    wmma::mma_sync(C[i][j], ah[i], bl[j], C[i][j]);
                    wmma::mma_sync(C[i][j], al[i], bh[j], C[i][j]);
                }
        }
        __syncthreads();
    }

    float* Cs = (float*)smem;
#pragma unroll
    for (int i = 0; i < 2; i++)
#pragma unroll
        for (int j = 0; j < 4; j++)
            wmma::store_matrix_sync(Cs + (wm * 32 + i * 16) * LDC + wn * 64 + j * 16,
                                    C[i][j], LDC, wmma::mem_row_major);
    __syncthreads();

    {
        const int r    = tid >> 1;
        const int half = tid & 1;
        const int m = m0 + r;
        const int s = m & 511, b = m >> 9;
        float* orow = g_xg + ((size_t)s * Bn + b) * Gsz;
        const float* crow = Cs + r * LDC + half * 64;
#pragma unroll
        for (int q = 0; q < 16; q++) {
            int n = n0 + half * 64 + q * 4;
            float4 v  = *(const float4*)(crow + q * 4);
            float4 b1 = *(const float4*)(b_ih + n);
            float4 b2 = *(const float4*)(b_hh + n);
            v.x += b1.x + b2.x; v.y += b1.y + b2.y;
            v.z += b1.z + b2.z; v.w += b1.w + b2.w;
            *(float4*)(orow + n) = v;
        }
    }
}

// ---------------------------------------------------------------------------
// Kernel 3: persistent recurrent LSTM. 256 threads (8 warps), 128 blocks =
// 4 b-columns x 32 j-slices; block = 16 j x 16 b (64 gate rows).
// Warp = (row-half of 32 rows) x (K-block of 128). Whi frags register-
// resident; Wlo permanent in smem. NEW: per-warp-pair h staging with NAMED
// barriers (bar.sync kh+1, 64) — each kh-pair stages only its own 128
// h-rows and starts MMA immediately; one fewer block-wide sync per step.
// ---------------------------------------------------------------------------
#define LDH  24                 // h smem ld (bf16)
#define LDCS 20                 // C partial ld (fp32)
#define LDWS 520                // W smem ld (bf16)
#define OFF_WLO  0                                      // bytes; permanent 66560
#define OFF_HHI  66560
#define OFF_HLO  (66560 + Hsz * LDH * 2)                // 91136
#define OFF_CS   (66560 + 2 * Hsz * LDH * 2)            // 115712
#define REC_SMEM_BYTES (OFF_CS + 4 * 64 * LDCS * 4)     // 136192

__global__ __launch_bounds__(256, 1) void lstm_rec_tc7(
    const float* __restrict__ h_n, const float* __restrict__ c_n,
    const float* __restrict__ W_hh, float* __restrict__ out)
{
    extern __shared__ char smem[];
    __nv_bfloat16* Wlo_s  = (__nv_bfloat16*)(smem + OFF_WLO);   // [64][LDWS] permanent
    __nv_bfloat16* Hhi_s  = (__nv_bfloat16*)(smem + OFF_HHI);   // [512][LDH]
    __nv_bfloat16* Hlo_s  = (__nv_bfloat16*)(smem + OFF_HLO);
    float*         Cs     = (float*)(smem + OFF_CS);            // [4][64][LDCS]
    __nv_bfloat16* WhiStg = (__nv_bfloat16*)(smem + OFF_HHI);   // init-only overlay

    const int tid = threadIdx.x;
    const int wid = tid >> 5;
    const int bs  = blockIdx.x & 3;        // b-column
    const int js  = blockIdx.x >> 2;       // j-slice
    unsigned* cnt = &g_cnt[bs * 32];

    // mma identity: warp -> (row-half, K-block)
    const int rt = wid & 1;                // rows rt*32 .. +31
    const int kh = wid >> 1;               // k kh*128 .. +127

    // ---- init: Wlo -> permanent smem, Whi -> staging, then frags -> regs ----
    for (int idx = tid; idx < 64 * Hsz; idx += 256) {
        int r = idx >> 9, k = idx & 511;
        float w = W_hh[((size_t)(r >> 4) * Hsz + js * JT + (r & 15)) * Hsz + k];
        __nv_bfloat16 hi = __float2bfloat16_rn(w);
        WhiStg[r * LDWS + k] = hi;
        Wlo_s [r * LDWS + k] = __float2bfloat16_rn(w - __bfloat162float(hi));
    }
    __syncthreads();

    wmma::fragment<wmma::matrix_a, 16, 16, 16, __nv_bfloat16, wmma::row_major> wa_hi[2][8];
#pragma unroll
    for (int mi = 0; mi < 2; mi++)
#pragma unroll
        for (int kk = 0; kk < 8; kk++)
            wmma::load_matrix_sync(wa_hi[mi][kk],
                WhiStg + (rt * 32 + mi * 16) * LDWS + kh * 128 + kk * 16, LDWS);
    __syncthreads();                       // done with Whi staging overlay

    // cell identity: tid = bb*16 + jj  (all 256 threads are cell threads)
    const int jj = tid & 15;
    const int bb = tid >> 4;
    const int j  = js * JT + jj;
    const int b  = bs * BT + bb;
    float c_reg = c_n[b * Hsz + j];
    {
        float h0 = h_n[b * Hsz + j];
        __nv_bfloat16 hi = __float2bfloat16_rn(h0);
        __nv_bfloat16 lo = __float2bfloat16_rn(h0 - __bfloat162float(hi));
        __stcg((unsigned short*)&g_hsl[0][bs][0][j * BT + bb], __bfloat16_as_ushort(hi));
        __stcg((unsigned short*)&g_hsl[0][bs][1][j * BT + bb], __bfloat16_as_ushort(lo));
    }
    __syncthreads();                       // h[0] stores done (cta scope)

    unsigned target = NJ;                  // one arrival per block
    if (tid == 0) {
        red_release(cnt);
        while (ld_acquire(cnt) < target) { }
    }
    __syncthreads();

    // prefetch xg[0]
    const float* xgp0 = g_xg + (size_t)b * Gsz + j;
    float xi = __ldcg(xgp0 + 0 * Hsz);
    float xf = __ldcg(xgp0 + 1 * Hsz);
    float xg = __ldcg(xgp0 + 2 * Hsz);
    float xo = __ldcg(xgp0 + 3 * Hsz);

    const int pairtid = tid & 63;          // thread index within kh-pair

    for (int t = 0; t < Ssz; t++) {
        // software-pipeline xg[t+1] (issue DRAM loads first)
        float nxi = 0.f, nxf = 0.f, nxg = 0.f, nxo = 0.f;
        if (t + 1 < Ssz) {
            const float* xgp = g_xg + ((size_t)(t + 1) * Bn + b) * Gsz + j;
            nxi = __ldcg(xgp + 0 * Hsz);
            nxf = __ldcg(xgp + 1 * Hsz);
            nxg = __ldcg(xgp + 2 * Hsz);
            nxo = __ldcg(xgp + 3 * Hsz);
        }

        // stage THIS kh-pair's 128 h-rows (rows kh*128..+127), 64 threads;
        // sync only the pair via named barrier, then go straight to MMA.
        {
            const uint4* shi = (const uint4*)g_hsl[t & 1][bs][0];
            const uint4* slo = (const uint4*)g_hsl[t & 1][bs][1];
#pragma unroll
            for (int it = 0; it < 4; it++) {
                int i = it * 64 + pairtid;     // 0..255 (uint4 within K-block)
                int r = i >> 1, half = i & 1;  // row within block, half-row
                int j2 = kh * 128 + r;
                int gidx = j2 * 2 + half;
                *(uint4*)(Hhi_s + j2 * LDH + half * 8) = __ldcg(shi + gidx);
                *(uint4*)(Hlo_s + j2 * LDH + half * 8) = __ldcg(slo + gidx);
            }
            asm volatile("bar.sync %0, 64;" :: "r"(kh + 1) : "memory");
        }

        // warp mma: 32 rows x 16 b over K=128; Whi from registers
        {
            wmma::fragment<wmma::accumulator, 16, 16, 16, float> chh[2], cx[2];
#pragma unroll
            for (int mi = 0; mi < 2; mi++) {
                wmma::fill_fragment(chh[mi], 0.0f);
                wmma::fill_fragment(cx[mi], 0.0f);
            }
#pragma unroll
            for (int kk = 0; kk < 8; kk++) {
                int k = kh * 128 + kk * 16;
                wmma::fragment<wmma::matrix_b, 16, 16, 16, __nv_bfloat16, wmma::row_major> bh, bl;
                wmma::load_matrix_sync(bh, Hhi_s + k * LDH, LDH);
                wmma::load_matrix_sync(bl, Hlo_s + k * LDH, LDH);
#pragma unroll
                for (int mi = 0; mi < 2; mi++) {
                    wmma::fragment<wmma::matrix_a, 16, 16, 16, __nv_bfloat16, wmma::row_major> wl;
                    wmma::load_matrix_sync(wl,
                        Wlo_s + (rt * 32 + mi * 16) * LDWS + k, LDWS);
                    wmma::mma_sync(chh[mi], wa_hi[mi][kk], bh, chh[mi]);
                    wmma::mma_sync(cx[mi],  wa_hi[mi][kk], bl, cx[mi]);
                    wmma::mma_sync(cx[mi],  wl, bh, cx[mi]);
                }
            }
#pragma unroll
            for (int mi = 0; mi < 2; mi++) {
#pragma unroll
                for (int i = 0; i < chh[mi].num_elements; i++)
                    chh[mi].x[i] += cx[mi].x[i];
                wmma::store_matrix_sync(
                    Cs + (kh * 64 + rt * 32 + mi * 16) * LDCS, chh[mi], LDCS,
                    wmma::mem_row_major);
            }
        }
        __syncthreads();                   // all Cs partials visible

        // elementwise LSTM cell; reduce 4 K-blocks
        {
            float gi = xi, gf = xf, gg = xg, go = xo;
#pragma unroll
            for (int q = 0; q < 4; q++) {
                const float* Cq = Cs + q * 64 * LDCS;
                gi += Cq[(0  + jj) * LDCS + bb];
                gf += Cq[(16 + jj) * LDCS + bb];
                gg += Cq[(32 + jj) * LDCS + bb];
                go += Cq[(48 + jj) * LDCS + bb];
            }
            float si = 1.f / (1.f + __expf(-gi));
            float sf = 1.f / (1.f + __expf(-gf));
            float so = 1.f / (1.f + __expf(-go));
            float tg = tanh_cheap(gg);
            c_reg = sf * c_reg + si * tg;
            float hnew = so * tanh_cheap(c_reg);

            __nv_bfloat16 hi = __float2bfloat16_rn(hnew);
            __nv_bfloat16 lo = __float2bfloat16_rn(hnew - __bfloat162float(hi));
            int pp = (t + 1) & 1;
            __stcg((unsigned short*)&g_hsl[pp][bs][0][j * BT + bb], __bfloat16_as_ushort(hi));
            __stcg((unsigned short*)&g_hsl[pp][bs][1][j * BT + bb], __bfloat16_as_ushort(lo));

            __stcg(&out[((size_t)b * Ssz + t) * Hsz + j], hnew);

            xi = nxi; xf = nxf; xg = nxg; xo = nxo;
        }
        __syncthreads();                   // publish stores happen-before arrival

        target += NJ;
        if (tid == 0) {
            red_release(cnt);              // release covers bar-synced stcg stores
            while (ld_acquire(cnt) < target) { }
        }
        __syncthreads();
    }

    // self-reset counters for next graph replay (last block chip-wide)
    if (tid == 0) {
        if (atomicAdd(&g_done, 1u) == NBS * NJ - 1) {
            for (int i = 0; i < NBS; i++) g_cnt[i * 32] = 0u;
            g_done = 0u;
            __threadfence();
        }
    }
}

// ---------------------------------------------------------------------------
// kernel_launch
// inputs: 0:x 1:emb 2:h_n 3:c_n 4:W_ih 5:W_hh 6:b_ih 7:b_hh
// Launch order: convert(1), dummy(2,3,4), gemm(5), lstm(6) — so ncu's
// "-s 5 -c 1" capture lands on lstm_rec_tc7.
// ---------------------------------------------------------------------------
extern "C" void kernel_launch(void* const* d_in, const int* in_sizes, int n_in,
                              void* d_out, int out_size)
{
    const float* x    = (const float*)d_in[0];
    const float* emb  = (const float*)d_in[1];
    const float* h_n  = (const float*)d_in[2];
    const float* c_n  = (const float*)d_in[3];
    const float* W_ih = (const float*)d_in[4];
    const float* W_hh = (const float*)d_in[5];
    const float* b_ih = (const float*)d_in[6];
    const float* b_hh = (const float*)d_in[7];
    float* out = (float*)d_out;

    cudaFuncSetAttribute(xg_gemm_mma, cudaFuncAttributeMaxDynamicSharedMemorySize,
                         SM_GEMM_BYTES);
    cudaFuncSetAttribute(lstm_rec_tc7, cudaFuncAttributeMaxDynamicSharedMemorySize,
                         REC_SMEM_BYTES);

    convert_kernel<<<1024, 256>>>(x, emb, W_ih);
    dummy_kernel<<<1, 1>>>();
    dummy_kernel<<<1, 1>>>();
    dummy_kernel<<<1, 1>>>();
    xg_gemm_mma<<<dim3(Gsz / GBN, (Bn * Ssz) / GBM), 256, SM_GEMM_BYTES>>>(b_ih, b_hh);
    lstm_rec_tc7<<<NBS * NJ, 256, REC_SMEM_BYTES>>>(h_n, c_n, W_hh, out);
}

// round 12
// speedup vs baseline: 1.0211x; 1.0211x over previous
#include <cuda_runtime.h>
#include <cuda_bf16.h>
#include <cuda_pipeline.h>
#include <mma.h>
#include <cstdint>

using namespace nvcuda;

#define Bn  64
#define Ssz 512
#define Dsz 512
#define Hsz 512
#define Gsz 2048   // 4*H

// recurrent tiling: 4 b-columns x 32 j-slices = 128 blocks, 256 threads each
#define NBS 4      // b-slices
#define NJ  32     // j-slice blocks per b-column
#define JT  16     // j per block
#define BT  16     // b per block

// ---------------------------------------------------------------------------
// global scratch
// ---------------------------------------------------------------------------
__device__ float         g_xg[(size_t)Ssz * Bn * Gsz];       // 256 MB
__device__ __nv_bfloat16 g_hsl[2][NBS][2][Hsz * BT];         // [ping][bs][hi/lo][j*16+bb]
__device__ unsigned      g_cnt[NBS * 32];                    // 128B-spaced counters
__device__ unsigned      g_done;
__device__ __nv_bfloat16 g_Ahi[(size_t)Bn * Ssz * Dsz];      // inputs hi
__device__ __nv_bfloat16 g_Alo[(size_t)Bn * Ssz * Dsz];      // inputs lo
__device__ __nv_bfloat16 g_Whi[(size_t)Gsz * Dsz];           // W_ih hi
__device__ __nv_bfloat16 g_Wlo[(size_t)Gsz * Dsz];           // W_ih lo

// ---------------------------------------------------------------------------
// light device-scope sync primitives (no membar.gl -> no L1 flush)
// ---------------------------------------------------------------------------
__device__ __forceinline__ void red_release(unsigned* p) {
    asm volatile("red.release.gpu.global.add.u32 [%0], 1;" :: "l"(p) : "memory");
}
__device__ __forceinline__ unsigned ld_acquire(unsigned* p) {
    unsigned v;
    asm volatile("ld.acquire.gpu.global.u32 %0, [%1];" : "=r"(v) : "l"(p) : "memory");
    return v;
}
// precise-enough tanh: 1 - 2/(e^{2x}+1); ~1e-6 rel err, 2 MUFU ops
__device__ __forceinline__ float tanh_cheap(float x) {
    return 1.0f - __fdividef(2.0f, __expf(2.0f * x) + 1.0f);
}

// ---------------------------------------------------------------------------
// dummy no-op kernel: with launch order conv(1), gemm(2), dummy(3), lstm(4),
// ncu's empirically-observed capture index (#4) lands on lstm_rec.
// ---------------------------------------------------------------------------
__global__ void dummy_kernel() { }

// ---------------------------------------------------------------------------
// Kernel 1: fp32 -> (hi,lo) bf16 split for inputs (with emb shift) and W_ih
// ---------------------------------------------------------------------------
__global__ __launch_bounds__(256) void convert_kernel(
    const float* __restrict__ x, const float* __restrict__ emb,
    const float* __restrict__ W_ih)
{
    const int A4 = (Bn * Ssz * Dsz) / 4;
    const int T4 = A4 + (Gsz * Dsz) / 4;
    for (int idx = blockIdx.x * 256 + threadIdx.x; idx < T4; idx += gridDim.x * 256) {
        const float* src;
        __nv_bfloat16 *hi, *lo;
        int off4;
        if (idx < A4) {
            int m = idx >> 7, c = idx & 127;
            int s = m & 511;
            src = (s == 0) ? (emb + (size_t)(m >> 9) * Dsz)
                           : (x + (size_t)(m - 1) * Dsz);
            src += c * 4;
            hi = g_Ahi; lo = g_Alo; off4 = idx;
        } else {
            int i2 = idx - A4;
            src = W_ih + (size_t)i2 * 4;
            hi = g_Whi; lo = g_Wlo; off4 = i2;
        }
        float4 v = *(const float4*)src;
        __nv_bfloat162 h01, h23, l01, l23;
        h01.x = __float2bfloat16_rn(v.x); h01.y = __float2bfloat16_rn(v.y);
        h23.x = __float2bfloat16_rn(v.z); h23.y = __float2bfloat16_rn(v.w);
        l01.x = __float2bfloat16_rn(v.x - __bfloat162float(h01.x));
        l01.y = __float2bfloat16_rn(v.y - __bfloat162float(h01.y));
        l23.x = __float2bfloat16_rn(v.z - __bfloat162float(h23.x));
        l23.y = __float2bfloat16_rn(v.w - __bfloat162float(h23.y));
        uint2 hu, lu;
        hu.x = *(uint32_t*)&h01; hu.y = *(uint32_t*)&h23;
        lu.x = *(uint32_t*)&l01; lu.y = *(uint32_t*)&l23;
        ((uint2*)hi)[off4] = hu;
        ((uint2*)lo)[off4] = lu;
    }
}

// ---------------------------------------------------------------------------
// Kernel 2: WMMA bf16 split GEMM  xg = inputs @ W_ih^T + (b_ih + b_hh)
// NEW: cp.async (LDGSTS) DOUBLE-BUFFERED pipeline — chunk k+1 streams into
// stage B while chunk k computes from stage A. Staging latency off the
// critical path; GEMM becomes HMMA-bound.
// ---------------------------------------------------------------------------
#define GBM 128
#define GBN 128
#define GKC 64
#define LDA 72
#define LDC 132
#define STG_ELE (4 * 128 * LDA)             // bf16 per stage (A_hi,A_lo,B_hi,B_lo)
#define SM_GEMM_BYTES (2 * STG_ELE * 2)     // 147456

__global__ __launch_bounds__(256) void xg_gemm_mma(
    const float* __restrict__ b_ih, const float* __restrict__ b_hh)
{
    extern __shared__ char smem[];

    const int tid = threadIdx.x;
    const int wid = tid >> 5;
    const int m0 = blockIdx.y * GBM;
    const int n0 = blockIdx.x * GBN;
    const int wm = wid >> 1;
    const int wn = wid & 1;

    auto stage_base = [&](int s) -> __nv_bfloat16* {
        return (__nv_bfloat16*)smem + s * STG_ELE;
    };
    auto load_chunk = [&](int kc, int s) {
        const int k0 = kc * GKC;
        __nv_bfloat16* base = stage_base(s);
#pragma unroll
        for (int u = 0; u < 4; u++) {
            int unit = u * 256 + tid;
            int row = unit >> 3, c8 = unit & 7;
            size_t ga = (size_t)(m0 + row) * Dsz + k0 + c8 * 8;
            size_t gb = (size_t)(n0 + row) * Dsz + k0 + c8 * 8;
            int so = row * LDA + c8 * 8;       // byte off = 144*row+16*c8 (16B-aligned)
            __pipeline_memcpy_async(base + so,                g_Ahi + ga, 16);
            __pipeline_memcpy_async(base + 128 * LDA + so,    g_Alo + ga, 16);
            __pipeline_memcpy_async(base + 2 * 128 * LDA + so, g_Whi + gb, 16);
            __pipeline_memcpy_async(base + 3 * 128 * LDA + so, g_Wlo + gb, 16);
        }
        __pipeline_commit();
    };

    wmma::fragment<wmma::accumulator, 16, 16, 16, float> C[2][4];
#pragma unroll
    for (int i = 0; i < 2; i++)
#pragma unroll
        for (int j = 0; j < 4; j++) wmma::fill_fragment(C[i][j], 0.0f);

    load_chunk(0, 0);

    for (int kc = 0; kc < Dsz / GKC; kc++) {
        if (kc + 1 < Dsz / GKC) load_chunk(kc + 1, (kc + 1) & 1);
        __pipeline_wait_prior((kc + 1 < Dsz / GKC) ? 1 : 0);
        __syncthreads();

        __nv_bfloat16* A_hi = stage_base(kc & 1);
        __nv_bfloat16* A_lo = A_hi + 128 * LDA;
        __nv_bfloat16* B_hi = A_lo + 128 * LDA;
        __nv_bfloat16* B_lo = B_hi + 128 * LDA;

#pragma unroll
        for (int kk = 0; kk < GKC / 16; kk++) {
            wmma::fragment<wmma::matrix_a, 16, 16, 16, __nv_bfloat16, wmma::row_major> ah[2], al[2];
            wmma::fragment<wmma::matrix_b, 16, 16, 16, __nv_bfloat16, wmma::col_major> bh[4], bl[4];
#pragma unroll
            for (int i = 0; i < 2; i++) {
                int ro = (wm * 32 + i * 16) * LDA + kk * 16;
                wmma::load_matrix_sync(ah[i], A_hi + ro, LDA);
                wmma::load_matrix_sync(al[i], A_lo + ro, LDA);
            }
#pragma unroll
            for (int j = 0; j < 4; j++) {
                int ro = (wn * 64 + j * 16) * LDA + kk * 16;
                wmma::load_matrix_sync(bh[j], B_hi + ro, LDA);
                wmma::load_matrix_sync(bl[j], B_lo + ro, LDA);
            }
#pragma unroll
            for (int i = 0; i < 2; i++)
#pragma unroll
                for (int j = 0; j < 4; j++) {
                    wmma::mma_sync(C[i][j], ah[i], bh[j], C[i][j]);
                    wmma::mma_sync(C[i][j], ah[i], bl[j], C[i][j]);
                    wmma::mma_sync(C[i][j], al[i], bh[j], C[i][j]);
                }
        }
        __syncthreads();
    }

    // epilogue: frags -> smem fp32 [128][LDC], then bias + store to g_xg
    float* Cs = (float*)smem;
#pragma unroll
    for (int i = 0; i < 2; i++)
#pragma unroll
        for (int j = 0; j < 4; j++)
            wmma::store_matrix_sync(Cs + (wm * 32 + i * 16) * LDC + wn * 64 + j * 16,
                                    C[i][j], LDC, wmma::mem_row_major);
    __syncthreads();

    {
        const int r    = tid >> 1;
        const int half = tid & 1;
        const int m = m0 + r;
        const int s = m & 511, b = m >> 9;
        float* orow = g_xg + ((size_t)s * Bn + b) * Gsz;
        const float* crow = Cs + r * LDC + half * 64;
#pragma unroll
        for (int q = 0; q < 16; q++) {
            int n = n0 + half * 64 + q * 4;
            float4 v  = *(const float4*)(crow + q * 4);
            float4 b1 = *(const float4*)(b_ih + n);
            float4 b2 = *(const float4*)(b_hh + n);
            v.x += b1.x + b2.x; v.y += b1.y + b2.y;
            v.z += b1.z + b2.z; v.w += b1.w + b2.w;
            *(float4*)(orow + n) = v;
        }
    }
}

// ---------------------------------------------------------------------------
// Kernel 3: persistent recurrent LSTM (unchanged from round 11).
// 256 threads (8 warps), 128 blocks = 4 b-columns x 32 j-slices.
// Whi frags register-resident; Wlo permanent smem; per-pair h staging with
// named barriers; one release-arrival per block + acquire poll.
// ---------------------------------------------------------------------------
#define LDH  24                 // h smem ld (bf16)
#define LDCS 20                 // C partial ld (fp32)
#define LDWS 520                // W smem ld (bf16)
#define OFF_WLO  0                                      // bytes; permanent 66560
#define OFF_HHI  66560
#define OFF_HLO  (66560 + Hsz * LDH * 2)                // 91136
#define OFF_CS   (66560 + 2 * Hsz * LDH * 2)            // 115712
#define REC_SMEM_BYTES (OFF_CS + 4 * 64 * LDCS * 4)     // 136192

__global__ __launch_bounds__(256, 1) void lstm_rec_tc7(
    const float* __restrict__ h_n, const float* __restrict__ c_n,
    const float* __restrict__ W_hh, float* __restrict__ out)
{
    extern __shared__ char smem[];
    __nv_bfloat16* Wlo_s  = (__nv_bfloat16*)(smem + OFF_WLO);   // [64][LDWS] permanent
    __nv_bfloat16* Hhi_s  = (__nv_bfloat16*)(smem + OFF_HHI);   // [512][LDH]
    __nv_bfloat16* Hlo_s  = (__nv_bfloat16*)(smem + OFF_HLO);
    float*         Cs     = (float*)(smem + OFF_CS);            // [4][64][LDCS]
    __nv_bfloat16* WhiStg = (__nv_bfloat16*)(smem + OFF_HHI);   // init-only overlay

    const int tid = threadIdx.x;
    const int wid = tid >> 5;
    const int bs  = blockIdx.x & 3;        // b-column
    const int js  = blockIdx.x >> 2;       // j-slice
    unsigned* cnt = &g_cnt[bs * 32];

    // mma identity: warp -> (row-half, K-block)
    const int rt = wid & 1;                // rows rt*32 .. +31
    const int kh = wid >> 1;               // k kh*128 .. +127

    // ---- init: Wlo -> permanent smem, Whi -> staging, then frags -> regs ----
    for (int idx = tid; idx < 64 * Hsz; idx += 256) {
        int r = idx >> 9, k = idx & 511;
        float w = W_hh[((size_t)(r >> 4) * Hsz + js * JT + (r & 15)) * Hsz + k];
        __nv_bfloat16 hi = __float2bfloat16_rn(w);
        WhiStg[r * LDWS + k] = hi;
        Wlo_s [r * LDWS + k] = __float2bfloat16_rn(w - __bfloat162float(hi));
    }
    __syncthreads();

    wmma::fragment<wmma::matrix_a, 16, 16, 16, __nv_bfloat16, wmma::row_major> wa_hi[2][8];
#pragma unroll
    for (int mi = 0; mi < 2; mi++)
#pragma unroll
        for (int kk = 0; kk < 8; kk++)
            wmma::load_matrix_sync(wa_hi[mi][kk],
                WhiStg + (rt * 32 + mi * 16) * LDWS + kh * 128 + kk * 16, LDWS);
    __syncthreads();                       // done with Whi staging overlay

    // cell identity: tid = bb*16 + jj  (all 256 threads are cell threads)
    const int jj = tid & 15;
    const int bb = tid >> 4;
    const int j  = js * JT + jj;
    const int b  = bs * BT + bb;
    float c_reg = c_n[b * Hsz + j];
    {
        float h0 = h_n[b * Hsz + j];
        __nv_bfloat16 hi = __float2bfloat16_rn(h0);
        __nv_bfloat16 lo = __float2bfloat16_rn(h0 - __bfloat162float(hi));
        __stcg((unsigned short*)&g_hsl[0][bs][0][j * BT + bb], __bfloat16_as_ushort(hi));
        __stcg((unsigned short*)&g_hsl[0][bs][1][j * BT + bb], __bfloat16_as_ushort(lo));
    }
    __syncthreads();                       // h[0] stores done (cta scope)

    unsigned target = NJ;                  // one arrival per block
    if (tid == 0) {
        red_release(cnt);
        while (ld_acquire(cnt) < target) { }
    }
    __syncthreads();

    // prefetch xg[0]
    const float* xgp0 = g_xg + (size_t)b * Gsz + j;
    float xi = __ldcg(xgp0 + 0 * Hsz);
    float xf = __ldcg(xgp0 + 1 * Hsz);
    float xg = __ldcg(xgp0 + 2 * Hsz);
    float xo = __ldcg(xgp0 + 3 * Hsz);

    const int pairtid = tid & 63;          // thread index within kh-pair

    for (int t = 0; t < Ssz; t++) {
        // software-pipeline xg[t+1] (issue DRAM loads first)
        float nxi = 0.f, nxf = 0.f, nxg = 0.f, nxo = 0.f;
        if (t + 1 < Ssz) {
            const float* xgp = g_xg + ((size_t)(t + 1) * Bn + b) * Gsz + j;
            nxi = __ldcg(xgp + 0 * Hsz);
            nxf = __ldcg(xgp + 1 * Hsz);
            nxg = __ldcg(xgp + 2 * Hsz);
            nxo = __ldcg(xgp + 3 * Hsz);
        }

        // stage THIS kh-pair's 128 h-rows; sync pair via named barrier.
        {
            const uint4* shi = (const uint4*)g_hsl[t & 1][bs][0];
            const uint4* slo = (const uint4*)g_hsl[t & 1][bs][1];
#pragma unroll
            for (int it = 0; it < 4; it++) {
                int i = it * 64 + pairtid;     // 0..255 (uint4 within K-block)
                int r = i >> 1, half = i & 1;
                int j2 = kh * 128 + r;
                int gidx = j2 * 2 + half;
                *(uint4*)(Hhi_s + j2 * LDH + half * 8) = __ldcg(shi + gidx);
                *(uint4*)(Hlo_s + j2 * LDH + half * 8) = __ldcg(slo + gidx);
            }
            asm volatile("bar.sync %0, 64;" :: "r"(kh + 1) : "memory");
        }

        // warp mma: 32 rows x 16 b over K=128; Whi from registers
        {
            wmma::fragment<wmma::accumulator, 16, 16, 16, float> chh[2], cx[2];
#pragma unroll
            for (int mi = 0; mi < 2; mi++) {
                wmma::fill_fragment(chh[mi], 0.0f);
                wmma::fill_fragment(cx[mi], 0.0f);
            }
#pragma unroll
            for (int kk = 0; kk < 8; kk++) {
                int k = kh * 128 + kk * 16;
                wmma::fragment<wmma::matrix_b, 16, 16, 16, __nv_bfloat16, wmma::row_major> bh, bl;
                wmma::load_matrix_sync(bh, Hhi_s + k * LDH, LDH);
                wmma::load_matrix_sync(bl, Hlo_s + k * LDH, LDH);
#pragma unroll
                for (int mi = 0; mi < 2; mi++) {
                    wmma::fragment<wmma::matrix_a, 16, 16, 16, __nv_bfloat16, wmma::row_major> wl;
                    wmma::load_matrix_sync(wl,
                        Wlo_s + (rt * 32 + mi * 16) * LDWS + k, LDWS);
                    wmma::mma_sync(chh[mi], wa_hi[mi][kk], bh, chh[mi]);
                    wmma::mma_sync(cx[mi],  wa_hi[mi][kk], bl, cx[mi]);
                    wmma::mma_sync(cx[mi],  wl, bh, cx[mi]);
                }
            }
#pragma unroll
            for (int mi = 0; mi < 2; mi++) {
#pragma unroll
                for (int i = 0; i < chh[mi].num_elements; i++)
                    chh[mi].x[i] += cx[mi].x[i];
                wmma::store_matrix_sync(
                    Cs + (kh * 64 + rt * 32 + mi * 16) * LDCS, chh[mi], LDCS,
                    wmma::mem_row_major);
            }
        }
        __syncthreads();                   // all Cs partials visible

        // elementwise LSTM cell; reduce 4 K-blocks
        {
            float gi = xi, gf = xf, gg = xg, go = xo;
#pragma unroll
            for (int q = 0; q < 4; q++) {
                const float* Cq = Cs + q * 64 * LDCS;
                gi += Cq[(0  + jj) * LDCS + bb];
                gf += Cq[(16 + jj) * LDCS + bb];
                gg += Cq[(32 + jj) * LDCS + bb];
                go += Cq[(48 + jj) * LDCS + bb];
            }
            float si = 1.f / (1.f + __expf(-gi));
            float sf = 1.f / (1.f + __expf(-gf));
            float so = 1.f / (1.f + __expf(-go));
            float tg = tanh_cheap(gg);
            c_reg = sf * c_reg + si * tg;
            float hnew = so * tanh_cheap(c_reg);

            __nv_bfloat16 hi = __float2bfloat16_rn(hnew);
            __nv_bfloat16 lo = __float2bfloat16_rn(hnew - __bfloat162float(hi));
            int pp = (t + 1) & 1;
            __stcg((unsigned short*)&g_hsl[pp][bs][0][j * BT + bb], __bfloat16_as_ushort(hi));
            __stcg((unsigned short*)&g_hsl[pp][bs][1][j * BT + bb], __bfloat16_as_ushort(lo));

            __stcg(&out[((size_t)b * Ssz + t) * Hsz + j], hnew);

            xi = nxi; xf = nxf; xg = nxg; xo = nxo;
        }
        __syncthreads();                   // publish stores happen-before arrival

        target += NJ;
        if (tid == 0) {
            red_release(cnt);              // release covers bar-synced stcg stores
            while (ld_acquire(cnt) < target) { }
        }
        __syncthreads();
    }

    // self-reset counters for next graph replay (last block chip-wide)
    if (tid == 0) {
        if (atomicAdd(&g_done, 1u) == NBS * NJ - 1) {
            for (int i = 0; i < NBS; i++) g_cnt[i * 32] = 0u;
            g_done = 0u;
            __threadfence();
        }
    }
}

// ---------------------------------------------------------------------------
// kernel_launch
// inputs: 0:x 1:emb 2:h_n 3:c_n 4:W_ih 5:W_hh 6:b_ih 7:b_hh
// Launch order: conv(1), gemm(2), dummy(3), lstm(4) — empirical ncu capture
// index is #4, so the recurrent kernel finally gets profiled.
// ---------------------------------------------------------------------------
extern "C" void kernel_launch(void* const* d_in, const int* in_sizes, int n_in,
                              void* d_out, int out_size)
{
    const float* x    = (const float*)d_in[0];
    const float* emb  = (const float*)d_in[1];
    const float* h_n  = (const float*)d_in[2];
    const float* c_n  = (const float*)d_in[3];
    const float* W_ih = (const float*)d_in[4];
    const float* W_hh = (const float*)d_in[5];
    const float* b_ih = (const float*)d_in[6];
    const float* b_hh = (const float*)d_in[7];
    float* out = (float*)d_out;

    cudaFuncSetAttribute(xg_gemm_mma, cudaFuncAttributeMaxDynamicSharedMemorySize,
                         SM_GEMM_BYTES);
    cudaFuncSetAttribute(lstm_rec_tc7, cudaFuncAttributeMaxDynamicSharedMemorySize,
                         REC_SMEM_BYTES);

    convert_kernel<<<1024, 256>>>(x, emb, W_ih);
    xg_gemm_mma<<<dim3(Gsz / GBN, (Bn * Ssz) / GBM), 256, SM_GEMM_BYTES>>>(b_ih, b_hh);
    dummy_kernel<<<1, 1>>>();
    lstm_rec_tc7<<<NBS * NJ, 256, REC_SMEM_BYTES>>>(h_n, c_n, W_hh, out);
}

// round 13
// speedup vs baseline: 1.0344x; 1.0131x over previous
#include <cuda_runtime.h>
#include <cuda_bf16.h>
#include <cuda_pipeline.h>
#include <mma.h>
#include <cstdint>

using namespace nvcuda;

#define Bn  64
#define Ssz 512
#define Dsz 512
#define Hsz 512
#define Gsz 2048   // 4*H

// recurrent tiling: 4 b-columns x 64 j-slices = 256 blocks, 128 threads each,
// 2 blocks per SM (co-residency = latency hiding).
#define NBS 4      // b-slices
#define NJ  64     // j-slice blocks per b-column
#define JT  8      // j per block
#define BT  16     // b per block

// ---------------------------------------------------------------------------
// global scratch
// ---------------------------------------------------------------------------
__device__ float         g_xg[(size_t)Ssz * Bn * Gsz];       // 256 MB
__device__ __nv_bfloat16 g_hsl[2][NBS][2][Hsz * BT];         // [ping][bs][hi/lo][j*16+bb]
__device__ unsigned      g_cnt[NBS * 32];                    // 128B-spaced counters
__device__ unsigned      g_done;
__device__ __nv_bfloat16 g_Ahi[(size_t)Bn * Ssz * Dsz];      // inputs hi
__device__ __nv_bfloat16 g_Alo[(size_t)Bn * Ssz * Dsz];      // inputs lo
__device__ __nv_bfloat16 g_Whi[(size_t)Gsz * Dsz];           // W_ih hi
__device__ __nv_bfloat16 g_Wlo[(size_t)Gsz * Dsz];           // W_ih lo

// ---------------------------------------------------------------------------
// light device-scope sync primitives (no membar.gl -> no L1 flush)
// ---------------------------------------------------------------------------
__device__ __forceinline__ void red_release(unsigned* p) {
    asm volatile("red.release.gpu.global.add.u32 [%0], 1;" :: "l"(p) : "memory");
}
__device__ __forceinline__ unsigned ld_acquire(unsigned* p) {
    unsigned v;
    asm volatile("ld.acquire.gpu.global.u32 %0, [%1];" : "=r"(v) : "l"(p) : "memory");
    return v;
}
// precise-enough tanh: 1 - 2/(e^{2x}+1); ~1e-6 rel err, 2 MUFU ops
__device__ __forceinline__ float tanh_cheap(float x) {
    return 1.0f - __fdividef(2.0f, __expf(2.0f * x) + 1.0f);
}

// dummy no-op: launch order conv(1), gemm(2), dummy(3), lstm(4) -> ncu's
// empirical capture index (#4) lands on the recurrent kernel.
__global__ void dummy_kernel() { }

// ---------------------------------------------------------------------------
// Kernel 1: fp32 -> (hi,lo) bf16 split for inputs (with emb shift) and W_ih
// ---------------------------------------------------------------------------
__global__ __launch_bounds__(256) void convert_kernel(
    const float* __restrict__ x, const float* __restrict__ emb,
    const float* __restrict__ W_ih)
{
    const int A4 = (Bn * Ssz * Dsz) / 4;
    const int T4 = A4 + (Gsz * Dsz) / 4;
    for (int idx = blockIdx.x * 256 + threadIdx.x; idx < T4; idx += gridDim.x * 256) {
        const float* src;
        __nv_bfloat16 *hi, *lo;
        int off4;
        if (idx < A4) {
            int m = idx >> 7, c = idx & 127;
            int s = m & 511;
            src = (s == 0) ? (emb + (size_t)(m >> 9) * Dsz)
                           : (x + (size_t)(m - 1) * Dsz);
            src += c * 4;
            hi = g_Ahi; lo = g_Alo; off4 = idx;
        } else {
            int i2 = idx - A4;
            src = W_ih + (size_t)i2 * 4;
            hi = g_Whi; lo = g_Wlo; off4 = i2;
        }
        float4 v = *(const float4*)src;
        __nv_bfloat162 h01, h23, l01, l23;
        h01.x = __float2bfloat16_rn(v.x); h01.y = __float2bfloat16_rn(v.y);
        h23.x = __float2bfloat16_rn(v.z); h23.y = __float2bfloat16_rn(v.w);
        l01.x = __float2bfloat16_rn(v.x - __bfloat162float(h01.x));
        l01.y = __float2bfloat16_rn(v.y - __bfloat162float(h01.y));
        l23.x = __float2bfloat16_rn(v.z - __bfloat162float(h23.x));
        l23.y = __float2bfloat16_rn(v.w - __bfloat162float(h23.y));
        uint2 hu, lu;
        hu.x = *(uint32_t*)&h01; hu.y = *(uint32_t*)&h23;
        lu.x = *(uint32_t*)&l01; lu.y = *(uint32_t*)&l23;
        ((uint2*)hi)[off4] = hu;
        ((uint2*)lo)[off4] = lu;
    }
}

// ---------------------------------------------------------------------------
// Kernel 2: WMMA bf16 split GEMM with cp.async double-buffered pipeline
// (unchanged from round 12)
// ---------------------------------------------------------------------------
#define GBM 128
#define GBN 128
#define GKC 64
#define LDA 72
#define LDC 132
#define STG_ELE (4 * 128 * LDA)
#define SM_GEMM_BYTES (2 * STG_ELE * 2)     // 147456

__global__ __launch_bounds__(256) void xg_gemm_mma(
    const float* __restrict__ b_ih, const float* __restrict__ b_hh)
{
    extern __shared__ char smem[];

    const int tid = threadIdx.x;
    const int wid = tid >> 5;
    const int m0 = blockIdx.y * GBM;
    const int n0 = blockIdx.x * GBN;
    const int wm = wid >> 1;
    const int wn = wid & 1;

    auto stage_base = [&](int s) -> __nv_bfloat16* {
        return (__nv_bfloat16*)smem + s * STG_ELE;
    };
    auto load_chunk = [&](int kc, int s) {
        const int k0 = kc * GKC;
        __nv_bfloat16* base = stage_base(s);
#pragma unroll
        for (int u = 0; u < 4; u++) {
            int unit = u * 256 + tid;
            int row = unit >> 3, c8 = unit & 7;
            size_t ga = (size_t)(m0 + row) * Dsz + k0 + c8 * 8;
            size_t gb = (size_t)(n0 + row) * Dsz + k0 + c8 * 8;
            int so = row * LDA + c8 * 8;
            __pipeline_memcpy_async(base + so,                 g_Ahi + ga, 16);
            __pipeline_memcpy_async(base + 128 * LDA + so,     g_Alo + ga, 16);
            __pipeline_memcpy_async(base + 2 * 128 * LDA + so, g_Whi + gb, 16);
            __pipeline_memcpy_async(base + 3 * 128 * LDA + so, g_Wlo + gb, 16);
        }
        __pipeline_commit();
    };

    wmma::fragment<wmma::accumulator, 16, 16, 16, float> C[2][4];
#pragma unroll
    for (int i = 0; i < 2; i++)
#pragma unroll
        for (int j = 0; j < 4; j++) wmma::fill_fragment(C[i][j], 0.0f);

    load_chunk(0, 0);

    for (int kc = 0; kc < Dsz / GKC; kc++) {
        if (kc + 1 < Dsz / GKC) load_chunk(kc + 1, (kc + 1) & 1);
        __pipeline_wait_prior((kc + 1 < Dsz / GKC) ? 1 : 0);
        __syncthreads();

        __nv_bfloat16* A_hi = stage_base(kc & 1);
        __nv_bfloat16* A_lo = A_hi + 128 * LDA;
        __nv_bfloat16* B_hi = A_lo + 128 * LDA;
        __nv_bfloat16* B_lo = B_hi + 128 * LDA;

#pragma unroll
        for (int kk = 0; kk < GKC / 16; kk++) {
            wmma::fragment<wmma::matrix_a, 16, 16, 16, __nv_bfloat16, wmma::row_major> ah[2], al[2];
            wmma::fragment<wmma::matrix_b, 16, 16, 16, __nv_bfloat16, wmma::col_major> bh[4], bl[4];
#pragma unroll
            for (int i = 0; i < 2; i++) {
                int ro = (wm * 32 + i * 16) * LDA + kk * 16;
                wmma::load_matrix_sync(ah[i], A_hi + ro, LDA);
                wmma::load_matrix_sync(al[i], A_lo + ro, LDA);
            }
#pragma unroll
            for (int j = 0; j < 4; j++) {
                int ro = (wn * 64 + j * 16) * LDA + kk * 16;
                wmma::load_matrix_sync(bh[j], B_hi + ro, LDA);
                wmma::load_matrix_sync(bl[j], B_lo + ro, LDA);
            }
#pragma unroll
            for (int i = 0; i < 2; i++)
#pragma unroll
                for (int j = 0; j < 4; j++) {
                    wmma::mma_sync(C[i][j], ah[i], bh[j], C[i][j]);
                    wmma::mma_sync(C[i][j], ah[i], bl[j], C[i][j]);
                    wmma::mma_sync(C[i][j], al[i], bh[j], C[i][j]);
                }
        }
        __syncthreads();
    }

    float* Cs = (float*)smem;
#pragma unroll
    for (int i = 0; i < 2; i++)
#pragma unroll
        for (int j = 0; j < 4; j++)
            wmma::store_matrix_sync(Cs + (wm * 32 + i * 16) * LDC + wn * 64 + j * 16,
                                    C[i][j], LDC, wmma::mem_row_major);
    __syncthreads();

    {
        const int r    = tid >> 1;
        const int half = tid & 1;
        const int m = m0 + r;
        const int s = m & 511, b = m >> 9;
        float* orow = g_xg + ((size_t)s * Bn + b) * Gsz;
        const float* crow = Cs + r * LDC + half * 64;
#pragma unroll
        for (int q = 0; q < 16; q++) {
            int n = n0 + half * 64 + q * 4;
            float4 v  = *(const float4*)(crow + q * 4);
            float4 b1 = *(const float4*)(b_ih + n);
            float4 b2 = *(const float4*)(b_hh + n);
            v.x += b1.x + b2.x; v.y += b1.y + b2.y;
            v.z += b1.z + b2.z; v.w += b1.w + b2.w;
            *(float4*)(orow + n) = v;
        }
    }
}

// ---------------------------------------------------------------------------
// Kernel 3: persistent recurrent LSTM. 256 blocks (4 cols x 64 slices),
// 128 threads (4 warps), 2 BLOCKS PER SM (launch_bounds(128,2), 92.7KB smem)
// -> co-resident independent blocks hide each other's barrier/memory stalls.
// Block = 8 j x 16 b = 32 gate-rows. Warp = all 32 rows x K-quarter (128).
// Whi frags register-resident (128 regs); Wlo in smem. Per-warp h staging
// (warp stages exactly the rows its LDSMs read -> __syncwarp only).
// ---------------------------------------------------------------------------
#define LDH  24                 // h smem ld (bf16)
#define LDCS 20                 // C partial ld (fp32)
#define LDWS 520                // W smem ld (bf16)
#define OFF_WLO  0                                       // 32*520*2 = 33280 B
#define OFF_HHI  33280
#define OFF_HLO  (33280 + Hsz * LDH * 2)                 // 57856
#define OFF_CS   (33280 + 2 * Hsz * LDH * 2)             // 82432
#define REC_SMEM_BYTES (OFF_CS + 4 * 32 * LDCS * 4)      // 92672

__global__ __launch_bounds__(128, 2) void lstm_rec_tc8(
    const float* __restrict__ h_n, const float* __restrict__ c_n,
    const float* __restrict__ W_hh, float* __restrict__ out)
{
    extern __shared__ char smem[];
    __nv_bfloat16* Wlo_s  = (__nv_bfloat16*)(smem + OFF_WLO);   // [32][LDWS] permanent
    __nv_bfloat16* Hhi_s  = (__nv_bfloat16*)(smem + OFF_HHI);   // [512][LDH]
    __nv_bfloat16* Hlo_s  = (__nv_bfloat16*)(smem + OFF_HLO);
    float*         Cs     = (float*)(smem + OFF_CS);            // [4][32][LDCS]
    __nv_bfloat16* WhiStg = (__nv_bfloat16*)(smem + OFF_HHI);   // init overlay (33KB<49KB)

    const int tid  = threadIdx.x;
    const int wid  = tid >> 5;
    const int lane = tid & 31;
    const int bs   = blockIdx.x >> 6;      // b-column (adjacent bids same col;
    const int js   = blockIdx.x & 63;      //  SM-paired bids differ by 148 -> diff col)
    unsigned* cnt = &g_cnt[bs * 32];

    const int kh = wid;                    // K quarter: kh*128 .. +127

    // ---- init: Wlo -> permanent smem, Whi -> staging overlay -> registers ----
    for (int idx = tid; idx < 32 * Hsz; idx += 128) {
        int r = idx >> 9, k = idx & 511;   // r = gate*8 + jj
        float w = W_hh[((size_t)(r >> 3) * Hsz + js * JT + (r & 7)) * Hsz + k];
        __nv_bfloat16 hi = __float2bfloat16_rn(w);
        WhiStg[r * LDWS + k] = hi;
        Wlo_s [r * LDWS + k] = __float2bfloat16_rn(w - __bfloat162float(hi));
    }
    __syncthreads();

    wmma::fragment<wmma::matrix_a, 16, 16, 16, __nv_bfloat16, wmma::row_major> wa_hi[2][8];
#pragma unroll
    for (int mi = 0; mi < 2; mi++)
#pragma unroll
        for (int kk = 0; kk < 8; kk++)
            wmma::load_matrix_sync(wa_hi[mi][kk],
                WhiStg + (mi * 16) * LDWS + kh * 128 + kk * 16, LDWS);
    __syncthreads();                       // done with Whi staging overlay

    // cell identity: tid = bb*8 + jj
    const int jj = tid & 7;
    const int bb = tid >> 3;
    const int j  = js * JT + jj;
    const int b  = bs * BT + bb;
    float c_reg = c_n[b * Hsz + j];
    {
        float h0 = h_n[b * Hsz + j];
        __nv_bfloat16 hi = __float2bfloat16_rn(h0);
        __nv_bfloat16 lo = __float2bfloat16_rn(h0 - __bfloat162float(hi));
        __stcg((unsigned short*)&g_hsl[0][bs][0][j * BT + bb], __bfloat16_as_ushort(hi));
        __stcg((unsigned short*)&g_hsl[0][bs][1][j * BT + bb], __bfloat16_as_ushort(lo));
    }
    __syncthreads();                       // h[0] stores done (cta scope)

    unsigned target = NJ;                  // one arrival per block
    if (tid == 0) {
        red_release(cnt);
        while (ld_acquire(cnt) < target) { }
    }
    __syncthreads();

    // prefetch xg[0]
    const float* xgp0 = g_xg + (size_t)b * Gsz + j;
    float xi = __ldcg(xgp0 + 0 * Hsz);
    float xf = __ldcg(xgp0 + 1 * Hsz);
    float xg = __ldcg(xgp0 + 2 * Hsz);
    float xo = __ldcg(xgp0 + 3 * Hsz);

    for (int t = 0; t < Ssz; t++) {
        // software-pipeline xg[t+1] (DRAM latency hidden behind mma)
        float nxi = 0.f, nxf = 0.f, nxg = 0.f, nxo = 0.f;
        if (t + 1 < Ssz) {
            const float* xgp = g_xg + ((size_t)(t + 1) * Bn + b) * Gsz + j;
            nxi = __ldcg(xgp + 0 * Hsz);
            nxf = __ldcg(xgp + 1 * Hsz);
            nxg = __ldcg(xgp + 2 * Hsz);
            nxo = __ldcg(xgp + 3 * Hsz);
        }

        // per-warp h staging: warp kh stages rows kh*128..+127 (its own
        // LDSM source rows) -> __syncwarp suffices, no block barrier.
        {
            const uint4* shi = (const uint4*)g_hsl[t & 1][bs][0];
            const uint4* slo = (const uint4*)g_hsl[t & 1][bs][1];
#pragma unroll
            for (int it = 0; it < 8; it++) {
                int i = it * 32 + lane;        // 0..255 (uint4 in K-quarter)
                int r = i >> 1, half = i & 1;
                int j2 = kh * 128 + r;
                int gidx = j2 * 2 + half;
                *(uint4*)(Hhi_s + j2 * LDH + half * 8) = __ldcg(shi + gidx);
                *(uint4*)(Hlo_s + j2 * LDH + half * 8) = __ldcg(slo + gidx);
            }
            __syncwarp();
        }

        // warp mma: 32 rows x 16 b over its K=128 quarter; Whi from regs
        {
            wmma::fragment<wmma::accumulator, 16, 16, 16, float> chh[2], cx[2];
#pragma unroll
            for (int mi = 0; mi < 2; mi++) {
                wmma::fill_fragment(chh[mi], 0.0f);
                wmma::fill_fragment(cx[mi], 0.0f);
            }
#pragma unroll
            for (int kk = 0; kk < 8; kk++) {
                int k = kh * 128 + kk * 16;
                wmma::fragment<wmma::matrix_b, 16, 16, 16, __nv_bfloat16, wmma::row_major> bh, bl;
                wmma::load_matrix_sync(bh, Hhi_s + k * LDH, LDH);
                wmma::load_matrix_sync(bl, Hlo_s + k * LDH, LDH);
#pragma unroll
                for (int mi = 0; mi < 2; mi++) {
                    wmma::fragment<wmma::matrix_a, 16, 16, 16, __nv_bfloat16, wmma::row_major> wl;
                    wmma::load_matrix_sync(wl, Wlo_s + (mi * 16) * LDWS + k, LDWS);
                    wmma::mma_sync(chh[mi], wa_hi[mi][kk], bh, chh[mi]);
                    wmma::mma_sync(cx[mi],  wa_hi[mi][kk], bl, cx[mi]);
                    wmma::mma_sync(cx[mi],  wl, bh, cx[mi]);
                }
            }
#pragma unroll
            for (int mi = 0; mi < 2; mi++) {
#pragma unroll
                for (int i = 0; i < chh[mi].num_elements; i++)
                    chh[mi].x[i] += cx[mi].x[i];
                wmma::store_matrix_sync(Cs + (kh * 32 + mi * 16) * LDCS, chh[mi],
                                        LDCS, wmma::mem_row_major);
            }
        }
        __syncthreads();                   // all Cs partials visible

        // elementwise LSTM cell; reduce 4 K-quarters
        {
            float gi = xi, gf = xf, gg = xg, go = xo;
#pragma unroll
            for (int q = 0; q < 4; q++) {
                const float* Cq = Cs + q * 32 * LDCS;
                gi += Cq[(0  + jj) * LDCS + bb];
                gf += Cq[(8  + jj) * LDCS + bb];
                gg += Cq[(16 + jj) * LDCS + bb];
                go += Cq[(24 + jj) * LDCS + bb];
            }
            float si = 1.f / (1.f + __expf(-gi));
            float sf = 1.f / (1.f + __expf(-gf));
            float so = 1.f / (1.f + __expf(-go));
            float tg = tanh_cheap(gg);
            c_reg = sf * c_reg + si * tg;
            float hnew = so * tanh_cheap(c_reg);

            __nv_bfloat16 hi = __float2bfloat16_rn(hnew);
            __nv_bfloat16 lo = __float2bfloat16_rn(hnew - __bfloat162float(hi));
            int pp = (t + 1) & 1;
            __stcg((unsigned short*)&g_hsl[pp][bs][0][j * BT + bb], __bfloat16_as_ushort(hi));
            __stcg((unsigned short*)&g_hsl[pp][bs][1][j * BT + bb], __bfloat16_as_ushort(lo));

            __stcg(&out[((size_t)b * Ssz + t) * Hsz + j], hnew);

            xi = nxi; xf = nxf; xg = nxg; xo = nxo;
        }
        __syncthreads();                   // publish stores happen-before arrival

        target += NJ;
        if (tid == 0) {
            red_release(cnt);              // release covers bar-synced stcg stores
            while (ld_acquire(cnt) < target) { }
        }
        __syncthreads();
    }

    // self-reset counters for next graph replay (last block chip-wide)
    if (tid == 0) {
        if (atomicAdd(&g_done, 1u) == NBS * NJ - 1) {
            for (int i = 0; i < NBS; i++) g_cnt[i * 32] = 0u;
            g_done = 0u;
            __threadfence();
        }
    }
}

// ---------------------------------------------------------------------------
// kernel_launch
// inputs: 0:x 1:emb 2:h_n 3:c_n 4:W_ih 5:W_hh 6:b_ih 7:b_hh
// Launch order: conv(1), gemm(2), dummy(3), lstm(4) — ncu capture lands on lstm.
// ---------------------------------------------------------------------------
extern "C" void kernel_launch(void* const* d_in, const int* in_sizes, int n_in,
                              void* d_out, int out_size)
{
    const float* x    = (const float*)d_in[0];
    const float* emb  = (const float*)d_in[1];
    const float* h_n  = (const float*)d_in[2];
    const float* c_n  = (const float*)d_in[3];
    const float* W_ih = (const float*)d_in[4];
    const float* W_hh = (const float*)d_in[5];
    const float* b_ih = (const float*)d_in[6];
    const float* b_hh = (const float*)d_in[7];
    float* out = (float*)d_out;

    cudaFuncSetAttribute(xg_gemm_mma, cudaFuncAttributeMaxDynamicSharedMemorySize,
                         SM_GEMM_BYTES);
    cudaFuncSetAttribute(lstm_rec_tc8, cudaFuncAttributeMaxDynamicSharedMemorySize,
                         REC_SMEM_BYTES);

    convert_kernel<<<1024, 256>>>(x, emb, W_ih);
    xg_gemm_mma<<<dim3(Gsz / GBN, (Bn * Ssz) / GBM), 256, SM_GEMM_BYTES>>>(b_ih, b_hh);
    dummy_kernel<<<1, 1>>>();
    lstm_rec_tc8<<<NBS * NJ, 128, REC_SMEM_BYTES>>>(h_n, c_n, W_hh, out);
}